// round 9
// baseline (speedup 1.0000x reference)
#include <cuda_runtime.h>
#include <cuda_bf16.h>
#include <cstdint>

// token_reprs: [B=32, L=512, H=768] f32 ; pos_idx: [B,E=32,M=8,S=4] i32
// out f32: entity [B,E,H] @0 ; mentions [B,E,M,H] @786432 ; mask [B,E,M] @7077888

#define B_ 32
#define L_ 512
#define H_ 768
#define E_ 32
#define M_ 8
#define S_ 4
#define HV (H_ / 4)          // 192 float4 per row
#define EG 8                 // entities per block (concurrent, one per warp)
#define NEG (E_ / EG)        // 4 entity-groups
#define CHUNK 32             // float4 columns per block (= warp width)
#define NCHUNK (HV / CHUNK)  // 6
#define IDXB (EG * M_ * S_)  // 256 indices per block

// Block = (batch, entity-group, column-chunk). 256 threads = 8 warps.
// Warp w = entity w of the group; lane = column. All 8 entities gather
// CONCURRENTLY -> duplicate rows across entities hit L1 in a tight temporal
// window (21% of draws are duplicates for 256 draws over 512 rows), cutting
// LTS read traffic without losing any parallelism (6144 warps, no barriers
// in the data path, entity sums thread-local).
__global__ __launch_bounds__(256, 6)
void entity_repr_kernel(const float* __restrict__ tok,
                        const int* __restrict__ pos,
                        float* __restrict__ ent,
                        float* __restrict__ men,
                        float* __restrict__ mask)
{
    __shared__ int sidx[IDXB];

    const int bx  = blockIdx.x;
    const int b   = bx / (NEG * NCHUNK);
    const int rem = bx % (NEG * NCHUNK);
    const int eg  = rem / NCHUNK;
    const int c   = rem % NCHUNK;

    const int t    = threadIdx.x;
    const int w    = t >> 5;            // entity within group
    const int lane = t & 31;            // column within chunk

    // 256 indices for this entity-group, one per thread
    sidx[t] = pos[(size_t)b * (E_ * M_ * S_) + eg * IDXB + t];
    __syncthreads();

    const int col = c * CHUNK + lane;   // global float4 column 0..191
    const int e   = eg * EG + w;        // global entity index

    const float4* __restrict__ tokb =
        reinterpret_cast<const float4*>(tok) + (size_t)b * L_ * HV + col;

    float4* __restrict__ men4 =
        reinterpret_cast<float4*>(men) + ((size_t)(b * E_ + e) * M_) * HV + col;
    float4* __restrict__ ent4 =
        reinterpret_cast<float4*>(ent) + (size_t)(b * E_ + e) * HV + col;

    const int* I = sidx + w * (M_ * S_);

    float ex = 0.f, ey = 0.f, ez = 0.f, ew_ = 0.f;

    #pragma unroll
    for (int m = 0; m < M_; m++) {
        const float4 v0 = tokb[(size_t)I[m * S_ + 0] * HV];
        const float4 v1 = tokb[(size_t)I[m * S_ + 1] * HV];
        const float4 v2 = tokb[(size_t)I[m * S_ + 2] * HV];
        const float4 v3 = tokb[(size_t)I[m * S_ + 3] * HV];

        float4 r;
        r.x = (v0.x + v1.x + v2.x + v3.x) * 0.25f;
        r.y = (v0.y + v1.y + v2.y + v3.y) * 0.25f;
        r.z = (v0.z + v1.z + v2.z + v3.z) * 0.25f;
        r.w = (v0.w + v1.w + v2.w + v3.w) * 0.25f;

        men4[(size_t)m * HV] = r;

        ex += r.x; ey += r.y; ez += r.z; ew_ += r.w;
    }

    float4 er;
    er.x = ex * 0.125f; er.y = ey * 0.125f;
    er.z = ez * 0.125f; er.w = ew_ * 0.125f;
    ent4[0] = er;

    // mask [B, E, M]: chunk-0 blocks write their group's 64 values
    if (c == 0 && t < EG * M_) {
        mask[(size_t)b * (E_ * M_) + eg * (EG * M_) + t] = 1.0f;
    }
}

extern "C" void kernel_launch(void* const* d_in, const int* in_sizes, int n_in,
                              void* d_out, int out_size)
{
    const float* tok = (const float*)d_in[0];
    const int*   pos = (const int*)d_in[1];

    float* out = (float*)d_out;
    float* ent  = out;                                  // 786432
    float* men  = out + (size_t)B_ * E_ * H_;           // +786432
    float* mask = men + (size_t)B_ * E_ * M_ * H_;      // +6291456

    entity_repr_kernel<<<B_ * NEG * NCHUNK, 256>>>(tok, pos, ent, men, mask);
}